// round 7
// baseline (speedup 1.0000x reference)
#include <cuda_runtime.h>
#include <cstdint>
#include <math.h>

// Q,K,V,O : [4,16,4096,64] fp32.
// out = rmsnorm( V * (1 + silu( rmsnorm(cumsum_s(silu(V)*V)) / (||Q||+||K||+1+2e-8) )) )
//
// Decoupled-lookback scan, 256 threads, CHUNK=64.
// Q/K streamed into SMEM via cp.async at kernel entry (DRAM busy from cycle 0);
// row norms computed from SMEM while lookback resolves. Phase B is global-load
// free: V + cumsums register-resident, r via LDS broadcast.

#define BH      64
#define SEQ     4096
#define DIM     64
#define CHUNK   64
#define NCHUNK  64
#define NGRP    16
#define NBLK    (BH * NCHUNK)   // 4096
#define QKPITCH 68              // floats per row in SMEM (pad vs bank conflicts)

__device__ float g_agg[NBLK * DIM];
__device__ int   g_flag[NBLK];

__device__ __forceinline__ float sigf(float x) {
    return __fdividef(1.0f, 1.0f + __expf(-x));
}
__device__ __forceinline__ float4 add4(float4 a, float4 b) {
    return make_float4(a.x + b.x, a.y + b.y, a.z + b.z, a.w + b.w);
}
__device__ __forceinline__ float4 sw4(float4 v) {
    return make_float4(v.x * v.x * sigf(v.x), v.y * v.y * sigf(v.y),
                       v.z * v.z * sigf(v.z), v.w * v.w * sigf(v.w));
}
__device__ __forceinline__ float dot4(float4 a) {
    return a.x * a.x + a.y * a.y + a.z * a.z + a.w * a.w;
}
__device__ __forceinline__ int ld_acq(const int* p) {
    int v;
    asm volatile("ld.global.acquire.gpu.b32 %0, [%1];" : "=r"(v) : "l"(p) : "memory");
    return v;
}
__device__ __forceinline__ void cp16(unsigned int dst, const void* src) {
    asm volatile("cp.async.cg.shared.global [%0], [%1], 16;" :: "r"(dst), "l"(src));
}

extern "C" __global__ void __launch_bounds__(256, 4)
k_fused(const float* __restrict__ Q, const float* __restrict__ K,
        const float* __restrict__ V, float* __restrict__ O)
{
    __shared__ float  qk[128 * QKPITCH];   // 34.8 KB: rows 0-63 Q, 64-127 K
    __shared__ float  gs[NGRP][QKPITCH];   //  4.25 KB group sums (scan transpose)
    __shared__ float  offs[NGRP][QKPITCH]; //  4.25 KB exclusive group prefixes
    __shared__ float4 basev[16];           //  chunk base from lookback
    __shared__ float  pre[4][DIM];         //  1 KB lookback partials
    __shared__ float  r_row[CHUNK];        //  per-row gate denominators

    const int blk = blockIdx.x;
    const int bh  = blk >> 6;
    const int ch  = blk & 63;
    const size_t cbase = ((size_t)bh * SEQ + (size_t)ch * CHUNK) * DIM;
    const int tid  = threadIdx.x;
    const int lane = tid & 31;
    const int w    = tid >> 5;
    const int q    = tid & 15;          // d-quad (channels 4q..4q+3)
    const int g    = tid >> 4;          // row group (rows 4g..4g+3)

    // ---------- Stream Q/K into SMEM asynchronously (no regs held) ----------
    {
        const int row = tid >> 1;          // 0..127
        const int hf  = tid & 1;           // half-row (32 floats)
        const float* src = (row < 64)
            ? (Q + cbase + (size_t)row * DIM + hf * 32)
            : (K + cbase + (size_t)(row - 64) * DIM + hf * 32);
        unsigned int dst = (unsigned int)__cvta_generic_to_shared(
            &qk[row * QKPITCH + hf * 32]);
        #pragma unroll
        for (int i = 0; i < 8; i++)
            cp16(dst + i * 16, src + i * 4);
        asm volatile("cp.async.commit_group;");
    }

    // ---------- Phase A: V loads + local cumsum (registers) ----------
    const float* vp = V + cbase + (size_t)(g * 4) * DIM + q * 4;
    float4 v0 = *(const float4*)(vp);
    float4 v1 = *(const float4*)(vp + DIM);
    float4 v2 = *(const float4*)(vp + 2 * DIM);
    float4 v3 = *(const float4*)(vp + 3 * DIM);

    float4 a0 = sw4(v0);
    float4 a1 = add4(a0, sw4(v1));
    float4 a2 = add4(a1, sw4(v2));
    float4 a3 = add4(a2, sw4(v3));
    *(float4*)&gs[g][q * 4] = a3;
    __syncthreads();

    // ---------- Warp-shuffle scan over 16 group sums ----------
    {
        const int seg = lane >> 4;
        const int sl  = lane & 15;          // group index in scan
        const int qq  = w * 2 + seg;        // d-quad this scan lane handles

        float4 incl = *(const float4*)&gs[sl][qq * 4];
        #pragma unroll
        for (int st = 1; st < 16; st <<= 1) {
            float4 t;
            t.x = __shfl_up_sync(0xFFFFFFFFu, incl.x, st);
            t.y = __shfl_up_sync(0xFFFFFFFFu, incl.y, st);
            t.z = __shfl_up_sync(0xFFFFFFFFu, incl.z, st);
            t.w = __shfl_up_sync(0xFFFFFFFFu, incl.w, st);
            if (sl >= st) incl = add4(incl, t);
        }
        if (sl == 15) {                      // publish chunk aggregate
            *(float4*)(g_agg + (size_t)blk * DIM + qq * 4) = incl;
            __threadfence();
        }
        float4 excl;
        excl.x = __shfl_up_sync(0xFFFFFFFFu, incl.x, 1);
        excl.y = __shfl_up_sync(0xFFFFFFFFu, incl.y, 1);
        excl.z = __shfl_up_sync(0xFFFFFFFFu, incl.z, 1);
        excl.w = __shfl_up_sync(0xFFFFFFFFu, incl.w, 1);
        if (sl == 0) excl = make_float4(0.f, 0.f, 0.f, 0.f);
        *(float4*)&offs[sl][qq * 4] = excl;
    }
    __syncthreads();
    if (tid == 0) atomicExch(&g_flag[blk], 1);   // release our successors ASAP

    // ---------- Q/K row norms from SMEM (hides our lookback wait) ----------
    asm volatile("cp.async.wait_group 0;");
    __syncthreads();
    {
        const int row = tid >> 2;            // 0..63
        const int p   = tid & 3;             // quarter of the row (16 floats)
        const float* qb = &qk[row * QKPITCH + p * 16];
        const float* kb = &qk[(row + 64) * QKPITCH + p * 16];
        float sq = 0.f, sk = 0.f;
        #pragma unroll
        for (int i = 0; i < 4; i++) {
            sq += dot4(*(const float4*)(qb + i * 4));
            sk += dot4(*(const float4*)(kb + i * 4));
        }
        sq += __shfl_xor_sync(0xFFFFFFFFu, sq, 1);
        sq += __shfl_xor_sync(0xFFFFFFFFu, sq, 2);
        sk += __shfl_xor_sync(0xFFFFFFFFu, sk, 1);
        sk += __shfl_xor_sync(0xFFFFFFFFu, sk, 2);
        if (p == 0)
            r_row[row] = sqrtf(sq) + sqrtf(sk) + 1.0f + 2e-8f;
    }

    // ---------- Lookback ----------
    if (ch > 0) {
        if (tid < ch) {
            const int* fp = g_flag + bh * NCHUNK + tid;
            while (ld_acq(fp) == 0) __nanosleep(32);
        }
        __syncthreads();
        {
            const int d = tid & 63, j = tid >> 6;
            float p = 0.f;
            for (int cc = j; cc < ch; cc += 4)
                p += __ldcg(g_agg + ((size_t)(bh * NCHUNK + cc)) * DIM + d);
            pre[j][d] = p;
        }
        __syncthreads();
        if (tid < 16) {
            float4 b;
            b.x = pre[0][tid*4+0] + pre[1][tid*4+0] + pre[2][tid*4+0] + pre[3][tid*4+0];
            b.y = pre[0][tid*4+1] + pre[1][tid*4+1] + pre[2][tid*4+1] + pre[3][tid*4+1];
            b.z = pre[0][tid*4+2] + pre[1][tid*4+2] + pre[2][tid*4+2] + pre[3][tid*4+2];
            b.w = pre[0][tid*4+3] + pre[1][tid*4+3] + pre[2][tid*4+3] + pre[3][tid*4+3];
            basev[tid] = b;
        }
    } else {
        if (tid < 16) basev[tid] = make_float4(0.f, 0.f, 0.f, 0.f);
    }
    __syncthreads();   // also orders r_row for phase B

    // Per-thread total offset: chunk base + exclusive cross-group prefix
    const float4 off4 = add4(*(const float4*)&offs[g][q * 4], basev[q]);

    // ---------- Phase B: no global loads; 16-lane butterflies ----------
    float4 av[4] = {a0, a1, a2, a3};
    float4 vv[4] = {v0, v1, v2, v3};

    #pragma unroll
    for (int j = 0; j < 4; j++) {
        const int s = g * 4 + j;
        const size_t roff = cbase + (size_t)s * DIM + q * 4;

        float4 c4 = add4(av[j], off4);
        float sc = dot4(c4);
        #pragma unroll
        for (int m = 8; m; m >>= 1)
            sc += __shfl_xor_sync(0xFFFFFFFFu, sc, m);

        float rms_c = rsqrtf(sc * (1.0f / DIM) + 1e-5f);
        float scale = __fdividef(rms_c, r_row[s]);   // LDS broadcast

        float m0 = c4.x * scale, m1 = c4.y * scale;
        float m2 = c4.z * scale, m3 = c4.w * scale;
        float4 v4 = vv[j];
        float o0 = v4.x * (1.0f + m0 * sigf(m0));
        float o1 = v4.y * (1.0f + m1 * sigf(m1));
        float o2 = v4.z * (1.0f + m2 * sigf(m2));
        float o3 = v4.w * (1.0f + m3 * sigf(m3));

        float so = o0 * o0 + o1 * o1 + o2 * o2 + o3 * o3;
        #pragma unroll
        for (int m = 8; m; m >>= 1)
            so += __shfl_xor_sync(0xFFFFFFFFu, so, m);

        float rms_o = rsqrtf(so * (1.0f / DIM) + 1e-5f);
        float4 out = make_float4(o0 * rms_o, o1 * rms_o, o2 * rms_o, o3 * rms_o);
        __stcs((float4*)(O + roff), out);
    }
}

// ---------------------------------------------------------------------------
extern "C" void kernel_launch(void* const* d_in, const int* in_sizes, int n_in,
                              void* d_out, int out_size) {
    const float* Q = (const float*)d_in[0];
    const float* K = (const float*)d_in[1];
    const float* V = (const float*)d_in[2];
    float* O = (float*)d_out;

    void* fp = nullptr;
    cudaGetSymbolAddress(&fp, g_flag);
    cudaMemsetAsync(fp, 0, NBLK * sizeof(int), 0);

    k_fused<<<NBLK, 256>>>(Q, K, V, O);
}

// round 8
// speedup vs baseline: 1.1605x; 1.1605x over previous
#include <cuda_runtime.h>
#include <cstdint>
#include <math.h>

// Q,K,V,O : [4,16,4096,64] fp32.
// out = rmsnorm( V * (1 + silu( rmsnorm(cumsum_s(silu(V)*V)) / (||Q||+||K||+1+2e-8) )) )
//
// R4 design (best measured) + chunk-major CTA ordering: blk = ch*64 + bh, so a
// chunk's scan predecessors are launched in earlier waves and the lookback
// spin almost always resolves instantly.

#define BH      64
#define SEQ     4096
#define DIM     64
#define CHUNK   64
#define NCHUNK  64
#define NGRP    16
#define NBLK    (BH * NCHUNK)   // 4096

__device__ float g_agg[NBLK * DIM];   // [bh][ch][d]
__device__ int   g_flag[NBLK];        // [bh][ch]

__device__ __forceinline__ float sigf(float x) {
    return __fdividef(1.0f, 1.0f + __expf(-x));
}
__device__ __forceinline__ float4 add4(float4 a, float4 b) {
    return make_float4(a.x + b.x, a.y + b.y, a.z + b.z, a.w + b.w);
}
__device__ __forceinline__ float4 sw4(float4 v) {
    return make_float4(v.x * v.x * sigf(v.x), v.y * v.y * sigf(v.y),
                       v.z * v.z * sigf(v.z), v.w * v.w * sigf(v.w));
}
__device__ __forceinline__ float dot4(float4 a) {
    return a.x * a.x + a.y * a.y + a.z * a.z + a.w * a.w;
}
__device__ __forceinline__ int ld_acq(const int* p) {
    int v;
    asm volatile("ld.global.acquire.gpu.b32 %0, [%1];" : "=r"(v) : "l"(p) : "memory");
    return v;
}

extern "C" __global__ void __launch_bounds__(256, 5)
k_fused(const float* __restrict__ Q, const float* __restrict__ K,
        const float* __restrict__ V, float* __restrict__ O)
{
    __shared__ float4 c_s[CHUNK][16];      // 16 KB: group-local cumsum
    __shared__ float  gs[NGRP][68];        // group sums (transpose buf)
    __shared__ float  offs[NGRP][68];      // per-group total offsets
    __shared__ float4 basev[16];           // chunk base prefix
    __shared__ float  pre[4][DIM];         // lookback partials

    const int blk = blockIdx.x;
    const int ch  = blk >> 6;              // chunk-major: predecessors launch earlier
    const int bh  = blk & 63;
    const int fbase = bh * NCHUNK;         // flag/agg row for this bh
    const size_t cbase = ((size_t)bh * SEQ + (size_t)ch * CHUNK) * DIM;
    const int tid  = threadIdx.x;
    const int lane = tid & 31;
    const int w    = tid >> 5;             // warp 0..7

    // ---------------- Phase A: per-group cumsum (4 rows/thread) ----------------
    {
        const int q = tid & 15;            // d-quad
        const int g = tid >> 4;            // group 0..15 (4 rows each)
        const float* vp = V + cbase + (size_t)(g * 4) * DIM + q * 4;
        float4 v0 = *(const float4*)(vp);
        float4 v1 = *(const float4*)(vp + DIM);
        float4 v2 = *(const float4*)(vp + 2 * DIM);
        float4 v3 = *(const float4*)(vp + 3 * DIM);

        float4 a0 = sw4(v0);
        float4 a1 = add4(a0, sw4(v1));
        float4 a2 = add4(a1, sw4(v2));
        float4 a3 = add4(a2, sw4(v3));
        c_s[g * 4 + 0][q] = a0;
        c_s[g * 4 + 1][q] = a1;
        c_s[g * 4 + 2][q] = a2;
        c_s[g * 4 + 3][q] = a3;
        *(float4*)&gs[g][q * 4] = a3;
    }
    __syncthreads();

    // ---------------- Warp-shuffle scan over 16 group sums ----------------
    const int seg = lane >> 4;
    const int sl  = lane & 15;
    const int qq  = w * 2 + seg;

    {
        float4 incl = *(const float4*)&gs[sl][qq * 4];
        #pragma unroll
        for (int st = 1; st < 16; st <<= 1) {
            float4 t;
            t.x = __shfl_up_sync(0xFFFFFFFFu, incl.x, st);
            t.y = __shfl_up_sync(0xFFFFFFFFu, incl.y, st);
            t.z = __shfl_up_sync(0xFFFFFFFFu, incl.z, st);
            t.w = __shfl_up_sync(0xFFFFFFFFu, incl.w, st);
            if (sl >= st) incl = add4(incl, t);
        }
        if (sl == 15) {
            *(float4*)(g_agg + ((size_t)fbase + ch) * DIM + qq * 4) = incl;
            __threadfence();
        }
        float4 excl;
        excl.x = __shfl_up_sync(0xFFFFFFFFu, incl.x, 1);
        excl.y = __shfl_up_sync(0xFFFFFFFFu, incl.y, 1);
        excl.z = __shfl_up_sync(0xFFFFFFFFu, incl.z, 1);
        excl.w = __shfl_up_sync(0xFFFFFFFFu, incl.w, 1);
        if (sl == 0) excl = make_float4(0.f, 0.f, 0.f, 0.f);
        *(float4*)&offs[sl][qq * 4] = excl;
    }
    __syncthreads();
    if (tid == 0) atomicExch(&g_flag[fbase + ch], 1);

    // ---------------- Lookback (usually instant: predecessors waves ahead) ----
    if (ch > 0) {
        if (tid < ch) {
            const int* fp = g_flag + fbase + tid;
            while (ld_acq(fp) == 0) __nanosleep(32);
        }
        __syncthreads();
        {
            const int d = tid & 63, j = tid >> 6;
            float p = 0.f;
            for (int cc = j; cc < ch; cc += 4)
                p += __ldcg(g_agg + ((size_t)(fbase + cc)) * DIM + d);
            pre[j][d] = p;
        }
        __syncthreads();
        if (tid < 16) {
            float4 b;
            b.x = pre[0][tid*4+0] + pre[1][tid*4+0] + pre[2][tid*4+0] + pre[3][tid*4+0];
            b.y = pre[0][tid*4+1] + pre[1][tid*4+1] + pre[2][tid*4+1] + pre[3][tid*4+1];
            b.z = pre[0][tid*4+2] + pre[1][tid*4+2] + pre[2][tid*4+2] + pre[3][tid*4+2];
            b.w = pre[0][tid*4+3] + pre[1][tid*4+3] + pre[2][tid*4+3] + pre[3][tid*4+3];
            basev[tid] = b;
        }
    } else {
        if (tid < 16) basev[tid] = make_float4(0.f, 0.f, 0.f, 0.f);
    }
    __syncthreads();

    // Per-group total offset = chunk base + exclusive group prefix
    {
        float4 o = add4(*(const float4*)&offs[sl][qq * 4], basev[qq]);
        *(float4*)&offs[sl][qq * 4] = o;
    }
    __syncthreads();

    // ---------------- Phase B: per-row math ----------------
    const int half = lane >> 4;
    const int l    = lane & 15;

    #pragma unroll
    for (int it = 0; it < 4; it++) {
        const int s   = w * 8 + it * 2 + half;   // row within chunk
        const int grp = s >> 2;
        const size_t roff = cbase + (size_t)s * DIM + l * 4;

        float4 q4 = __ldcs((const float4*)(Q + roff));
        float4 k4 = __ldcs((const float4*)(K + roff));
        float4 v4 = *(const float4*)(V + roff);         // L1 hit
        float4 c4 = add4(c_s[s][l], *(const float4*)&offs[grp][l * 4]);

        float sq = dot4(q4);
        float sk = dot4(k4);
        float sc = dot4(c4);
        #pragma unroll
        for (int m = 8; m; m >>= 1) {
            sq += __shfl_xor_sync(0xFFFFFFFFu, sq, m);
            sk += __shfl_xor_sync(0xFFFFFFFFu, sk, m);
            sc += __shfl_xor_sync(0xFFFFFFFFu, sc, m);
        }

        float rms_c = rsqrtf(sc * (1.0f / DIM) + 1e-5f);
        float r     = sqrtf(sq) + sqrtf(sk) + 1.0f + 2e-8f;
        float scale = __fdividef(rms_c, r);

        float m0 = c4.x * scale, m1 = c4.y * scale;
        float m2 = c4.z * scale, m3 = c4.w * scale;
        float o0 = v4.x * (1.0f + m0 * sigf(m0));
        float o1 = v4.y * (1.0f + m1 * sigf(m1));
        float o2 = v4.z * (1.0f + m2 * sigf(m2));
        float o3 = v4.w * (1.0f + m3 * sigf(m3));

        float so = o0 * o0 + o1 * o1 + o2 * o2 + o3 * o3;
        #pragma unroll
        for (int m = 8; m; m >>= 1)
            so += __shfl_xor_sync(0xFFFFFFFFu, so, m);

        float rms_o = rsqrtf(so * (1.0f / DIM) + 1e-5f);
        float4 out = make_float4(o0 * rms_o, o1 * rms_o, o2 * rms_o, o3 * rms_o);
        __stcs((float4*)(O + roff), out);
    }
}

// ---------------------------------------------------------------------------
extern "C" void kernel_launch(void* const* d_in, const int* in_sizes, int n_in,
                              void* d_out, int out_size) {
    const float* Q = (const float*)d_in[0];
    const float* K = (const float*)d_in[1];
    const float* V = (const float*)d_in[2];
    float* O = (float*)d_out;

    void* fp = nullptr;
    cudaGetSymbolAddress(&fp, g_flag);
    cudaMemsetAsync(fp, 0, NBLK * sizeof(int), 0);

    k_fused<<<NBLK, 256>>>(Q, K, V, O);
}

// round 9
// speedup vs baseline: 1.2596x; 1.0854x over previous
#include <cuda_runtime.h>
#include <cstdint>
#include <math.h>

// Q,K,V,O : [4,16,4096,64] fp32.
// out = rmsnorm( V * (1 + silu( rmsnorm(cumsum_s(silu(V)*V)) / (||Q||+||K||+1+2e-8) )) )
//
// Decoupled-lookback scan (chunk-major CTA order) + wide phase B:
// each lane owns 8 channels -> 8-lane row reductions (3 shfl steps), 4 rows
// per warp-iteration. SHFL count in phase B cut 2.7x vs previous round.

#define BH      64
#define SEQ     4096
#define DIM     64
#define CHUNK   64
#define NCHUNK  64
#define NGRP    16
#define NBLK    (BH * NCHUNK)   // 4096

__device__ float g_agg[NBLK * DIM];   // [bh][ch][d]
__device__ int   g_flag[NBLK];        // [bh][ch]

__device__ __forceinline__ float sigf(float x) {
    return __fdividef(1.0f, 1.0f + __expf(-x));
}
__device__ __forceinline__ float4 add4(float4 a, float4 b) {
    return make_float4(a.x + b.x, a.y + b.y, a.z + b.z, a.w + b.w);
}
__device__ __forceinline__ float4 sw4(float4 v) {
    return make_float4(v.x * v.x * sigf(v.x), v.y * v.y * sigf(v.y),
                       v.z * v.z * sigf(v.z), v.w * v.w * sigf(v.w));
}
__device__ __forceinline__ float dot4(float4 a) {
    return a.x * a.x + a.y * a.y + a.z * a.z + a.w * a.w;
}
__device__ __forceinline__ int ld_acq(const int* p) {
    int v;
    asm volatile("ld.global.acquire.gpu.b32 %0, [%1];" : "=r"(v) : "l"(p) : "memory");
    return v;
}

extern "C" __global__ void __launch_bounds__(256, 5)
k_fused(const float* __restrict__ Q, const float* __restrict__ K,
        const float* __restrict__ V, float* __restrict__ O)
{
    __shared__ float4 c_s[CHUNK][16];      // 16 KB: group-local cumsum
    __shared__ float  gs[NGRP][68];        // group sums (transpose buf)
    __shared__ float  offs[NGRP][68];      // per-group total offsets
    __shared__ float4 basev[16];           // chunk base prefix
    __shared__ float  pre[4][DIM];         // lookback partials

    const int blk = blockIdx.x;
    const int ch  = blk >> 6;              // chunk-major launch order
    const int bh  = blk & 63;
    const int fbase = bh * NCHUNK;
    const size_t cbase = ((size_t)bh * SEQ + (size_t)ch * CHUNK) * DIM;
    const int tid  = threadIdx.x;
    const int lane = tid & 31;
    const int w    = tid >> 5;

    // ---------------- Phase A: per-group cumsum (4 rows/thread) ----------------
    {
        const int q = tid & 15;            // d-quad
        const int g = tid >> 4;            // group 0..15 (4 rows each)
        const float* vp = V + cbase + (size_t)(g * 4) * DIM + q * 4;
        float4 v0 = *(const float4*)(vp);
        float4 v1 = *(const float4*)(vp + DIM);
        float4 v2 = *(const float4*)(vp + 2 * DIM);
        float4 v3 = *(const float4*)(vp + 3 * DIM);

        float4 a0 = sw4(v0);
        float4 a1 = add4(a0, sw4(v1));
        float4 a2 = add4(a1, sw4(v2));
        float4 a3 = add4(a2, sw4(v3));
        c_s[g * 4 + 0][q] = a0;
        c_s[g * 4 + 1][q] = a1;
        c_s[g * 4 + 2][q] = a2;
        c_s[g * 4 + 3][q] = a3;
        *(float4*)&gs[g][q * 4] = a3;
    }
    __syncthreads();

    // ---------------- Warp-shuffle scan over 16 group sums ----------------
    const int seg = lane >> 4;
    const int sl  = lane & 15;
    const int qq  = w * 2 + seg;

    {
        float4 incl = *(const float4*)&gs[sl][qq * 4];
        #pragma unroll
        for (int st = 1; st < 16; st <<= 1) {
            float4 t;
            t.x = __shfl_up_sync(0xFFFFFFFFu, incl.x, st);
            t.y = __shfl_up_sync(0xFFFFFFFFu, incl.y, st);
            t.z = __shfl_up_sync(0xFFFFFFFFu, incl.z, st);
            t.w = __shfl_up_sync(0xFFFFFFFFu, incl.w, st);
            if (sl >= st) incl = add4(incl, t);
        }
        if (sl == 15) {
            *(float4*)(g_agg + ((size_t)fbase + ch) * DIM + qq * 4) = incl;
            __threadfence();
        }
        float4 excl;
        excl.x = __shfl_up_sync(0xFFFFFFFFu, incl.x, 1);
        excl.y = __shfl_up_sync(0xFFFFFFFFu, incl.y, 1);
        excl.z = __shfl_up_sync(0xFFFFFFFFu, incl.z, 1);
        excl.w = __shfl_up_sync(0xFFFFFFFFu, incl.w, 1);
        if (sl == 0) excl = make_float4(0.f, 0.f, 0.f, 0.f);
        *(float4*)&offs[sl][qq * 4] = excl;
    }
    __syncthreads();
    if (tid == 0) atomicExch(&g_flag[fbase + ch], 1);

    // ---------------- Lookback ----------------
    if (ch > 0) {
        if (tid < ch) {
            const int* fp = g_flag + fbase + tid;
            while (ld_acq(fp) == 0) __nanosleep(32);
        }
        __syncthreads();
        {
            const int d = tid & 63, j = tid >> 6;
            float p = 0.f;
            for (int cc = j; cc < ch; cc += 4)
                p += __ldcg(g_agg + ((size_t)(fbase + cc)) * DIM + d);
            pre[j][d] = p;
        }
        __syncthreads();
        if (tid < 16) {
            float4 b;
            b.x = pre[0][tid*4+0] + pre[1][tid*4+0] + pre[2][tid*4+0] + pre[3][tid*4+0];
            b.y = pre[0][tid*4+1] + pre[1][tid*4+1] + pre[2][tid*4+1] + pre[3][tid*4+1];
            b.z = pre[0][tid*4+2] + pre[1][tid*4+2] + pre[2][tid*4+2] + pre[3][tid*4+2];
            b.w = pre[0][tid*4+3] + pre[1][tid*4+3] + pre[2][tid*4+3] + pre[3][tid*4+3];
            basev[tid] = b;
        }
    } else {
        if (tid < 16) basev[tid] = make_float4(0.f, 0.f, 0.f, 0.f);
    }
    __syncthreads();

    // Per-group total offset = chunk base + exclusive group prefix
    {
        float4 o = add4(*(const float4*)&offs[sl][qq * 4], basev[qq]);
        *(float4*)&offs[sl][qq * 4] = o;
    }
    __syncthreads();

    // ---------------- Phase B: 8-lane rows, 4 rows/warp-iteration ----------------
    const int rid = lane >> 3;        // row slot 0..3
    const int l8  = lane & 7;         // channels 8*l8 .. 8*l8+7

    #pragma unroll
    for (int it = 0; it < 2; it++) {
        const int s   = w * 8 + it * 4 + rid;   // row within chunk
        const int grp = s >> 2;
        const size_t roff = cbase + (size_t)s * DIM + l8 * 8;

        float4 qa = __ldcs((const float4*)(Q + roff));
        float4 qb = __ldcs((const float4*)(Q + roff + 4));
        float4 ka = __ldcs((const float4*)(K + roff));
        float4 kb = __ldcs((const float4*)(K + roff + 4));
        float4 va = *(const float4*)(V + roff);        // L1 hit
        float4 vb = *(const float4*)(V + roff + 4);
        float4 ca = add4(c_s[s][l8 * 2 + 0], *(const float4*)&offs[grp][l8 * 8 + 0]);
        float4 cb = add4(c_s[s][l8 * 2 + 1], *(const float4*)&offs[grp][l8 * 8 + 4]);

        float sq = dot4(qa) + dot4(qb);
        float sk = dot4(ka) + dot4(kb);
        float sc = dot4(ca) + dot4(cb);
        #pragma unroll
        for (int m = 4; m; m >>= 1) {              // 8-lane butterfly
            sq += __shfl_xor_sync(0xFFFFFFFFu, sq, m);
            sk += __shfl_xor_sync(0xFFFFFFFFu, sk, m);
            sc += __shfl_xor_sync(0xFFFFFFFFu, sc, m);
        }

        float rms_c = rsqrtf(sc * (1.0f / DIM) + 1e-5f);
        float r     = sqrtf(sq) + sqrtf(sk) + 1.0f + 2e-8f;
        float scale = __fdividef(rms_c, r);

        float m0 = ca.x * scale, m1 = ca.y * scale;
        float m2 = ca.z * scale, m3 = ca.w * scale;
        float m4 = cb.x * scale, m5 = cb.y * scale;
        float m6 = cb.z * scale, m7 = cb.w * scale;
        float o0 = va.x * (1.0f + m0 * sigf(m0));
        float o1 = va.y * (1.0f + m1 * sigf(m1));
        float o2 = va.z * (1.0f + m2 * sigf(m2));
        float o3 = va.w * (1.0f + m3 * sigf(m3));
        float o4 = vb.x * (1.0f + m4 * sigf(m4));
        float o5 = vb.y * (1.0f + m5 * sigf(m5));
        float o6 = vb.z * (1.0f + m6 * sigf(m6));
        float o7 = vb.w * (1.0f + m7 * sigf(m7));

        float so = o0*o0 + o1*o1 + o2*o2 + o3*o3 + o4*o4 + o5*o5 + o6*o6 + o7*o7;
        #pragma unroll
        for (int m = 4; m; m >>= 1)
            so += __shfl_xor_sync(0xFFFFFFFFu, so, m);

        float rms_o = rsqrtf(so * (1.0f / DIM) + 1e-5f);
        float4 oa = make_float4(o0 * rms_o, o1 * rms_o, o2 * rms_o, o3 * rms_o);
        float4 ob = make_float4(o4 * rms_o, o5 * rms_o, o6 * rms_o, o7 * rms_o);
        __stcs((float4*)(O + roff), oa);
        __stcs((float4*)(O + roff + 4), ob);
    }
}

// ---------------------------------------------------------------------------
extern "C" void kernel_launch(void* const* d_in, const int* in_sizes, int n_in,
                              void* d_out, int out_size) {
    const float* Q = (const float*)d_in[0];
    const float* K = (const float*)d_in[1];
    const float* V = (const float*)d_in[2];
    float* O = (float*)d_out;

    void* fp = nullptr;
    cudaGetSymbolAddress(&fp, g_flag);
    cudaMemsetAsync(fp, 0, NBLK * sizeof(int), 0);

    k_fused<<<NBLK, 256>>>(Q, K, V, O);
}